// round 4
// baseline (speedup 1.0000x reference)
#include <cuda_runtime.h>
#include <math.h>
#include <stdint.h>

#define T_TOK 8192
#define H_DIM 2048
#define I_DIM 1408
#define E_NUM 16
#define TOPK  2
#define NSLOT (T_TOK * TOPK)

#define BM 128
#define BN 128
#define BK 32
#define SROW 44                       // padded floats per smem row (176B, 16B-aligned)
#define ARR (128 * SROW)              // floats per tile array (5632)

// ----------------------------- device scratch --------------------------------
__device__ float g_h  [(size_t)NSLOT * I_DIM];   // w * silu(xW1)*(xUp), tf32-rounded
__device__ float g_o2 [(size_t)NSLOT * H_DIM];   // per-slot GEMM2 output
__device__ int   g_top2[T_TOK * 2];
__device__ float g_wts [T_TOK * 2];
__device__ int   g_cnt [E_NUM];
__device__ int   g_off [E_NUM + 1];
__device__ int   g_tok [NSLOT];
__device__ float g_slotw[NSLOT];
__device__ int   g_slot[T_TOK * 2];

// ----------------------------- helpers ---------------------------------------
__device__ __forceinline__ uint32_t smem_u32(const void* p) {
    uint32_t a;
    asm("{ .reg .u64 t; cvta.to.shared.u64 t, %1; cvt.u32.u64 %0, t; }" : "=r"(a) : "l"(p));
    return a;
}
__device__ __forceinline__ float to_tf32(float x) {
    uint32_t r;
    asm("cvt.rna.tf32.f32 %0, %1;" : "=r"(r) : "f"(x));
    return __uint_as_float(r);
}
__device__ __forceinline__ uint32_t to_tf32_u(float x) {
    uint32_t r;
    asm("cvt.rna.tf32.f32 %0, %1;" : "=r"(r) : "f"(x));
    return r;
}
__device__ __forceinline__ void cp16(uint32_t dst, const float* src) {
    asm volatile("cp.async.cg.shared.global [%0], [%1], 16;"
                 :: "r"(dst), "l"(__cvta_generic_to_global(src)) : "memory");
}
#define CP_COMMIT() asm volatile("cp.async.commit_group;" ::: "memory")
#define CP_WAIT(n)  asm volatile("cp.async.wait_group %0;" :: "n"(n) : "memory")

// m16n8k8 tf32 mma: d += a * b  (row.col; A 16x8, B col-major 8x8, C fp32)
#define MMA_TF32(d, a, b)                                                      \
    asm volatile("mma.sync.aligned.m16n8k8.row.col.f32.tf32.tf32.f32 "         \
        "{%0,%1,%2,%3}, {%4,%5,%6,%7}, {%8,%9}, {%0,%1,%2,%3};"                \
        : "+f"((d)[0]), "+f"((d)[1]), "+f"((d)[2]), "+f"((d)[3])               \
        : "r"((a)[0]), "r"((a)[1]), "r"((a)[2]), "r"((a)[3]),                  \
          "r"((b)[0]), "r"((b)[1]))

__device__ __forceinline__ float silu_mul(float a, float u) {
    return (a / (1.f + __expf(-a))) * u;
}

// ----------------------------- setup ------------------------------------------
__global__ void reset_kernel() {
    int i = threadIdx.x;
    if (i < E_NUM) g_cnt[i] = 0;
}

// ----------------------------- gate: gw staged in smem ------------------------
// 256 blocks x 256 threads; 32 tokens per block (warp handles 4 tokens).
__global__ __launch_bounds__(256)
void gate_kernel(const float* __restrict__ x, const float* __restrict__ gw) {
    extern __shared__ float sgw[];           // E_NUM * H_DIM floats = 128 KB
    int tid = threadIdx.x;
    for (int i = tid; i < E_NUM * H_DIM / 4; i += 256)
        ((float4*)sgw)[i] = ((const float4*)gw)[i];
    __syncthreads();

    int warp = tid >> 5, lane = tid & 31;
#pragma unroll
    for (int i = 0; i < 4; i++) {
        int t = blockIdx.x * 32 + warp * 4 + i;
        const float* xr = x + (size_t)t * H_DIM;
        float acc[E_NUM];
#pragma unroll
        for (int e = 0; e < E_NUM; e++) acc[e] = 0.f;
        for (int k = lane * 2; k < H_DIM; k += 64) {
            float2 xv = *(const float2*)(xr + k);
#pragma unroll
            for (int e = 0; e < E_NUM; e++) {
                float2 g = *(const float2*)(sgw + e * H_DIM + k);
                acc[e] += xv.x * g.x + xv.y * g.y;
            }
        }
#pragma unroll
        for (int e = 0; e < E_NUM; e++) {
#pragma unroll
            for (int off = 16; off > 0; off >>= 1)
                acc[e] += __shfl_xor_sync(0xFFFFFFFFu, acc[e], off);
        }
        if (lane == 0) {
            int e1 = 0; float l1 = acc[0];
#pragma unroll
            for (int e = 1; e < E_NUM; e++) if (acc[e] > l1) { l1 = acc[e]; e1 = e; }
            int e2 = -1; float l2 = -INFINITY;
#pragma unroll
            for (int e = 0; e < E_NUM; e++)
                if (e != e1 && acc[e] > l2) { l2 = acc[e]; e2 = e; }
            float p2  = expf(l2 - l1);
            float inv = 1.f / (1.f + p2);
            g_top2[t * 2] = e1; g_top2[t * 2 + 1] = e2;
            g_wts[t * 2] = inv; g_wts[t * 2 + 1] = p2 * inv;
            atomicAdd(&g_cnt[e1], 1);
            atomicAdd(&g_cnt[e2], 1);
        }
    }
}

// ----------------------------- scatter (single block, incl. offsets) ----------
__global__ __launch_bounds__(1024)
void scatter_kernel() {
    __shared__ int s_fill[E_NUM];
    int tid = threadIdx.x;
    if (tid < E_NUM) s_fill[tid] = 0;
    if (tid == 0) {
        int s = 0;
        for (int e = 0; e < E_NUM; e++) { g_off[e] = s; s += g_cnt[e]; }
        g_off[E_NUM] = s;
    }
    __syncthreads();
    for (int t = tid; t < T_TOK; t += 1024) {
#pragma unroll
        for (int kk = 0; kk < TOPK; kk++) {
            int e = g_top2[t * 2 + kk];
            int p = atomicAdd(&s_fill[e], 1);
            int slot = g_off[e] + p;
            g_tok[slot]   = t;
            g_slotw[slot] = g_wts[t * 2 + kk];
            g_slot[t * 2 + kk] = slot;
        }
    }
}

// ----------------------------- GEMM1 (tf32 mma.sync, dual accum) -------------
// h[slot, I] = tf32( w_slot * silu(x W1^T) * (x Up^T) ),  C-tile 128x128, K=2048
__global__ __launch_bounds__(512, 1)
void gemm1_mma(const float* __restrict__ gx, const float* __restrict__ gW1,
               const float* __restrict__ gUp) {
    extern __shared__ float sm[];
    const int STG = 3 * ARR;

    int e = blockIdx.z;
    int base = g_off[e], count = g_off[e + 1] - base;
    int m0 = blockIdx.y * BM;
    if (m0 >= count) return;
    int n0 = blockIdx.x * BN;

    int tid = threadIdx.x;
    int wid = tid >> 5, lane = tid & 31;
    int warpM = wid >> 2, warpN = wid & 3;
    int g = lane >> 2, tig = lane & 3;

    int r0 = tid >> 3;
    int colf = (tid & 7) * 4;
    int mr0 = m0 + r0;          if (mr0 > count - 1) mr0 = count - 1;
    int mr1 = m0 + r0 + 64;     if (mr1 > count - 1) mr1 = count - 1;
    int t0 = g_tok[base + mr0];
    int t1 = g_tok[base + mr1];
    const float* A0  = gx  + (size_t)t0 * H_DIM + colf;
    const float* A1  = gx  + (size_t)t1 * H_DIM + colf;
    const float* B1a = gW1 + ((size_t)e * I_DIM + n0 + r0)      * H_DIM + colf;
    const float* B1b = gW1 + ((size_t)e * I_DIM + n0 + r0 + 64) * H_DIM + colf;
    const float* B2a = gUp + ((size_t)e * I_DIM + n0 + r0)      * H_DIM + colf;
    const float* B2b = gUp + ((size_t)e * I_DIM + n0 + r0 + 64) * H_DIM + colf;

    uint32_t sb = smem_u32(sm);
    uint32_t o0 = (uint32_t)(r0 * SROW + colf) * 4u;
    uint32_t o1 = (uint32_t)((r0 + 64) * SROW + colf) * 4u;

    float accA[2][4][4], accU[2][4][4];
#pragma unroll
    for (int mt = 0; mt < 2; mt++)
#pragma unroll
        for (int nt = 0; nt < 4; nt++)
#pragma unroll
            for (int j = 0; j < 4; j++) { accA[mt][nt][j] = 0.f; accU[mt][nt][j] = 0.f; }

    const int KT = H_DIM / BK;   // 64

#define G1_LOAD(s, kt) do {                                                    \
        uint32_t stgb = sb + (uint32_t)(s) * STG * 4u;                         \
        int ko = (kt) * BK;                                                    \
        cp16(stgb + o0,                 A0  + ko);                             \
        cp16(stgb + o1,                 A1  + ko);                             \
        cp16(stgb + ARR * 4u + o0,      B1a + ko);                             \
        cp16(stgb + ARR * 4u + o1,      B1b + ko);                             \
        cp16(stgb + 2u * ARR * 4u + o0, B2a + ko);                             \
        cp16(stgb + 2u * ARR * 4u + o1, B2b + ko);                             \
    } while (0)

    G1_LOAD(0, 0); CP_COMMIT();
    G1_LOAD(1, 1); CP_COMMIT();

    for (int kt = 0; kt < KT; kt++) {
        CP_WAIT(1);
        __syncthreads();
        if (kt + 2 < KT) {
            int s2 = (kt + 2) % 3;
            G1_LOAD(s2, kt + 2);
        }
        CP_COMMIT();

        const float* S   = sm + (kt % 3) * STG;
        const float* SA  = S;
        const float* SB1 = S + ARR;
        const float* SB2 = S + 2 * ARR;

#pragma unroll
        for (int ks = 0; ks < 4; ks++) {
            int k = ks * 8;
            uint32_t a[2][4];
#pragma unroll
            for (int mt = 0; mt < 2; mt++) {
                int row = warpM * 32 + mt * 16 + g;
                a[mt][0] = to_tf32_u(SA[row * SROW + k + tig]);
                a[mt][1] = to_tf32_u(SA[(row + 8) * SROW + k + tig]);
                a[mt][2] = to_tf32_u(SA[row * SROW + k + tig + 4]);
                a[mt][3] = to_tf32_u(SA[(row + 8) * SROW + k + tig + 4]);
            }
#pragma unroll
            for (int nt = 0; nt < 4; nt++) {
                int col = warpN * 32 + nt * 8 + g;
                uint32_t b1[2], b2[2];
                b1[0] = to_tf32_u(SB1[col * SROW + k + tig]);
                b1[1] = to_tf32_u(SB1[col * SROW + k + tig + 4]);
                b2[0] = to_tf32_u(SB2[col * SROW + k + tig]);
                b2[1] = to_tf32_u(SB2[col * SROW + k + tig + 4]);
#pragma unroll
                for (int mt = 0; mt < 2; mt++) {
                    MMA_TF32(accA[mt][nt], a[mt], b1);
                    MMA_TF32(accU[mt][nt], a[mt], b2);
                }
            }
        }
    }
#undef G1_LOAD

    // epilogue: w * silu(accA) * accU -> g_h (tf32-rounded)
#pragma unroll
    for (int mt = 0; mt < 2; mt++) {
        int row = m0 + warpM * 32 + mt * 16 + g;
        float w0 = (row < count)     ? g_slotw[base + row]     : 0.f;
        float w1 = (row + 8 < count) ? g_slotw[base + row + 8] : 0.f;
#pragma unroll
        for (int nt = 0; nt < 4; nt++) {
            int col = n0 + warpN * 32 + nt * 8 + 2 * tig;
            if (row < count) {
                float2 v;
                v.x = to_tf32(w0 * silu_mul(accA[mt][nt][0], accU[mt][nt][0]));
                v.y = to_tf32(w0 * silu_mul(accA[mt][nt][1], accU[mt][nt][1]));
                *(float2*)(g_h + (size_t)(base + row) * I_DIM + col) = v;
            }
            if (row + 8 < count) {
                float2 v;
                v.x = to_tf32(w1 * silu_mul(accA[mt][nt][2], accU[mt][nt][2]));
                v.y = to_tf32(w1 * silu_mul(accA[mt][nt][3], accU[mt][nt][3]));
                *(float2*)(g_h + (size_t)(base + row + 8) * I_DIM + col) = v;
            }
        }
    }
}

// ----------------------------- GEMM2 (tf32 mma.sync) -------------------------
// o2[slot, H] = h W2^T,  C-tile 128x128, K = 1408
__global__ __launch_bounds__(512, 1)
void gemm2_mma(const float* __restrict__ gW2) {
    extern __shared__ float sm[];
    const int STG = 2 * ARR;

    int e = blockIdx.z;
    int base = g_off[e], count = g_off[e + 1] - base;
    int m0 = blockIdx.y * BM;
    if (m0 >= count) return;
    int n0 = blockIdx.x * BN;

    int tid = threadIdx.x;
    int wid = tid >> 5, lane = tid & 31;
    int warpM = wid >> 2, warpN = wid & 3;
    int g = lane >> 2, tig = lane & 3;

    int r0 = tid >> 3;
    int colf = (tid & 7) * 4;
    int mr0 = m0 + r0;          if (mr0 > count - 1) mr0 = count - 1;
    int mr1 = m0 + r0 + 64;     if (mr1 > count - 1) mr1 = count - 1;
    const float* A0 = g_h + (size_t)(base + mr0) * I_DIM + colf;
    const float* A1 = g_h + (size_t)(base + mr1) * I_DIM + colf;
    const float* Ba = gW2 + ((size_t)e * H_DIM + n0 + r0)      * I_DIM + colf;
    const float* Bb = gW2 + ((size_t)e * H_DIM + n0 + r0 + 64) * I_DIM + colf;

    uint32_t sb = smem_u32(sm);
    uint32_t o0 = (uint32_t)(r0 * SROW + colf) * 4u;
    uint32_t o1 = (uint32_t)((r0 + 64) * SROW + colf) * 4u;

    float acc[2][4][4];
#pragma unroll
    for (int mt = 0; mt < 2; mt++)
#pragma unroll
        for (int nt = 0; nt < 4; nt++)
#pragma unroll
            for (int j = 0; j < 4; j++) acc[mt][nt][j] = 0.f;

    const int KT = I_DIM / BK;   // 44

#define G2_LOAD(s, kt) do {                                                    \
        uint32_t stgb = sb + (uint32_t)(s) * STG * 4u;                         \
        int ko = (kt) * BK;                                                    \
        cp16(stgb + o0,            A0 + ko);                                   \
        cp16(stgb + o1,            A1 + ko);                                   \
        cp16(stgb + ARR * 4u + o0, Ba + ko);                                   \
        cp16(stgb + ARR * 4u + o1, Bb + ko);                                   \
    } while (0)

    G2_LOAD(0, 0); CP_COMMIT();
    G2_LOAD(1, 1); CP_COMMIT();
    G2_LOAD(2, 2); CP_COMMIT();

    for (int kt = 0; kt < KT; kt++) {
        CP_WAIT(2);
        __syncthreads();
        if (kt + 3 < KT) {
            int s2 = (kt + 3) & 3;
            G2_LOAD(s2, kt + 3);
        }
        CP_COMMIT();

        const float* S  = sm + (kt & 3) * STG;
        const float* SA = S;
        const float* SB = S + ARR;

#pragma unroll
        for (int ks = 0; ks < 4; ks++) {
            int k = ks * 8;
            uint32_t a[2][4];
#pragma unroll
            for (int mt = 0; mt < 2; mt++) {
                int row = warpM * 32 + mt * 16 + g;
                a[mt][0] = __float_as_uint(SA[row * SROW + k + tig]);
                a[mt][1] = __float_as_uint(SA[(row + 8) * SROW + k + tig]);
                a[mt][2] = __float_as_uint(SA[row * SROW + k + tig + 4]);
                a[mt][3] = __float_as_uint(SA[(row + 8) * SROW + k + tig + 4]);
            }
#pragma unroll
            for (int nt = 0; nt < 4; nt++) {
                int col = warpN * 32 + nt * 8 + g;
                uint32_t b[2];
                b[0] = to_tf32_u(SB[col * SROW + k + tig]);
                b[1] = to_tf32_u(SB[col * SROW + k + tig + 4]);
#pragma unroll
                for (int mt = 0; mt < 2; mt++) MMA_TF32(acc[mt][nt], a[mt], b);
            }
        }
    }
#undef G2_LOAD

#pragma unroll
    for (int mt = 0; mt < 2; mt++) {
#pragma unroll
        for (int nt = 0; nt < 4; nt++) {
            int row = m0 + warpM * 32 + mt * 16 + g;
            int col = n0 + warpN * 32 + nt * 8 + 2 * tig;
            if (row < count) {
                float2 v = make_float2(acc[mt][nt][0], acc[mt][nt][1]);
                *(float2*)(g_o2 + (size_t)(base + row) * H_DIM + col) = v;
            }
            if (row + 8 < count) {
                float2 v = make_float2(acc[mt][nt][2], acc[mt][nt][3]);
                *(float2*)(g_o2 + (size_t)(base + row + 8) * H_DIM + col) = v;
            }
        }
    }
}

// ----------------------------- combine (weights pre-folded) ------------------
__global__ void combine_kernel(float4* __restrict__ out) {
    int idx = blockIdx.x * blockDim.x + threadIdx.x;
    int t = idx >> 9;          // H/4 = 512
    int c = idx & 511;
    const float4* r0 = (const float4*)(g_o2 + (size_t)g_slot[t * 2]     * H_DIM) + c;
    const float4* r1 = (const float4*)(g_o2 + (size_t)g_slot[t * 2 + 1] * H_DIM) + c;
    float4 a = *r0, b = *r1, v;
    v.x = a.x + b.x;
    v.y = a.y + b.y;
    v.z = a.z + b.z;
    v.w = a.w + b.w;
    out[idx] = v;
}

// ----------------------------- launch -----------------------------------------
extern "C" void kernel_launch(void* const* d_in, const int* in_sizes, int n_in,
                              void* d_out, int out_size) {
    const float* x  = (const float*)d_in[0];
    const float* gw = (const float*)d_in[1];
    const float* W1 = (const float*)d_in[2];
    const float* Up = (const float*)d_in[3];
    const float* W2 = (const float*)d_in[4];
    float* out = (float*)d_out;

    const int SMEMG = E_NUM * H_DIM * 4;   // 131,072 B (gate)
    const int SMEM1 = 3 * 3 * ARR * 4;     // 202,752 B
    const int SMEM2 = 4 * 2 * ARR * 4;     // 180,224 B
    cudaFuncSetAttribute(gate_kernel, cudaFuncAttributeMaxDynamicSharedMemorySize, SMEMG);
    cudaFuncSetAttribute(gemm1_mma,  cudaFuncAttributeMaxDynamicSharedMemorySize, SMEM1);
    cudaFuncSetAttribute(gemm2_mma,  cudaFuncAttributeMaxDynamicSharedMemorySize, SMEM2);

    reset_kernel<<<1, 32>>>();                       // 0
    gate_kernel<<<T_TOK / 32, 256, SMEMG>>>(x, gw);  // 1
    scatter_kernel<<<1, 1024>>>();                   // 2

    dim3 g1(I_DIM / BN, T_TOK / BM, E_NUM);          // 3  (11, 64, 16)
    gemm1_mma<<<g1, 512, SMEM1>>>(x, W1, Up);

    dim3 g2(H_DIM / BN, T_TOK / BM, E_NUM);          // 4  (16, 64, 16)
    gemm2_mma<<<g2, 512, SMEM2>>>(W2);

    combine_kernel<<<(T_TOK * H_DIM / 4) / 256, 256>>>((float4*)out);  // 5
}

// round 5
// speedup vs baseline: 1.7653x; 1.7653x over previous
#include <cuda_runtime.h>
#include <cuda_fp16.h>
#include <math.h>
#include <stdint.h>

#define T_TOK 8192
#define H_DIM 2048
#define I_DIM 1408
#define E_NUM 16
#define TOPK  2
#define NSLOT (T_TOK * TOPK)

#define BM 128
#define BN 64
#define BK 64                 // halves per K-slab (128 B/row)
#define SROW2 72              // padded halves per smem row (144 B)
#define A_BYTES (128 * SROW2 * 2)       // 18432
#define B_BYTES (64  * SROW2 * 2)       // 9216
#define STG1_B (A_BYTES + 2 * B_BYTES)  // 36864 (gemm1 stage: A,B1,B2)
#define STG2_B (A_BYTES + B_BYTES)      // 27648 (gemm2 stage: A,B)

// ----------------------------- device scratch --------------------------------
__device__ __half g_xh [(size_t)T_TOK * H_DIM];
__device__ __half g_w1h[(size_t)E_NUM * I_DIM * H_DIM];
__device__ __half g_uph[(size_t)E_NUM * I_DIM * H_DIM];
__device__ __half g_w2h[(size_t)E_NUM * H_DIM * I_DIM];
__device__ __half g_h  [(size_t)NSLOT * I_DIM];     // w * silu(xW1)*(xUp)
__device__ float  g_o2 [(size_t)NSLOT * H_DIM];
__device__ int    g_top2[T_TOK * 2];
__device__ float  g_wts [T_TOK * 2];
__device__ int    g_off [E_NUM + 1];
__device__ int    g_tok [NSLOT];
__device__ float  g_slotw[NSLOT];
__device__ int    g_slot[T_TOK * 2];

// ----------------------------- helpers ---------------------------------------
__device__ __forceinline__ uint32_t smem_u32(const void* p) {
    uint32_t a;
    asm("{ .reg .u64 t; cvta.to.shared.u64 t, %1; cvt.u32.u64 %0, t; }" : "=r"(a) : "l"(p));
    return a;
}
__device__ __forceinline__ void cp16(uint32_t dst, const void* src) {
    asm volatile("cp.async.cg.shared.global [%0], [%1], 16;"
                 :: "r"(dst), "l"(__cvta_generic_to_global(src)) : "memory");
}
#define CP_COMMIT() asm volatile("cp.async.commit_group;" ::: "memory")
#define CP_WAIT(n)  asm volatile("cp.async.wait_group %0;" :: "n"(n) : "memory")

// m16n8k16 fp16 mma, fp32 accum (row.col)
#define MMA_F16(d, a, b)                                                       \
    asm volatile("mma.sync.aligned.m16n8k16.row.col.f32.f16.f16.f32 "          \
        "{%0,%1,%2,%3}, {%4,%5,%6,%7}, {%8,%9}, {%0,%1,%2,%3};"                \
        : "+f"((d)[0]), "+f"((d)[1]), "+f"((d)[2]), "+f"((d)[3])               \
        : "r"((a)[0]), "r"((a)[1]), "r"((a)[2]), "r"((a)[3]),                  \
          "r"((b)[0]), "r"((b)[1]))

__device__ __forceinline__ float silu_mul(float a, float u) {
    return (a / (1.f + __expf(-a))) * u;
}
__device__ __forceinline__ uint32_t lds_u32(const __half* p) {
    return *(const uint32_t*)p;
}

// ----------------------------- fp16 weight conversion ------------------------
__global__ void f2h_all(const float4* __restrict__ w1, const float4* __restrict__ up,
                        const float4* __restrict__ w2) {
    const long n4 = (long)E_NUM * I_DIM * H_DIM / 4;   // 11,534,336
    long i = blockIdx.x * (long)blockDim.x + threadIdx.x;
    long stride = (long)gridDim.x * blockDim.x;
    for (; i < 3 * n4; i += stride) {
        const float4* src;
        __half* dsth;
        long j;
        if (i < n4)            { src = w1 + i;          dsth = g_w1h; j = i; }
        else if (i < 2 * n4)   { src = up + (i - n4);   dsth = g_uph; j = i - n4; }
        else                   { src = w2 + (i - 2*n4); dsth = g_w2h; j = i - 2*n4; }
        float4 v = *src;
        __half2 h01 = __floats2half2_rn(v.x, v.y);
        __half2 h23 = __floats2half2_rn(v.z, v.w);
        uint2 u;
        u.x = *(uint32_t*)&h01;
        u.y = *(uint32_t*)&h23;
        *(uint2*)(dsth + j * 4) = u;
    }
}

// ----------------------------- gate (+ x -> fp16) ----------------------------
__global__ __launch_bounds__(256)
void gate_kernel(const float* __restrict__ x, const float* __restrict__ gw) {
    extern __shared__ float sgw[];           // E_NUM * H_DIM floats = 128 KB
    int tid = threadIdx.x;
    for (int i = tid; i < E_NUM * H_DIM / 4; i += 256)
        ((float4*)sgw)[i] = ((const float4*)gw)[i];
    __syncthreads();

    int warp = tid >> 5, lane = tid & 31;
#pragma unroll
    for (int i = 0; i < 4; i++) {
        int t = blockIdx.x * 32 + warp * 4 + i;
        const float* xr = x + (size_t)t * H_DIM;
        float acc[E_NUM];
#pragma unroll
        for (int e = 0; e < E_NUM; e++) acc[e] = 0.f;
        for (int k = lane * 2; k < H_DIM; k += 64) {
            float2 xv = *(const float2*)(xr + k);
            __half2 hv = __floats2half2_rn(xv.x, xv.y);
            *(__half2*)(g_xh + (size_t)t * H_DIM + k) = hv;
#pragma unroll
            for (int e = 0; e < E_NUM; e++) {
                float2 g = *(const float2*)(sgw + e * H_DIM + k);
                acc[e] += xv.x * g.x + xv.y * g.y;
            }
        }
#pragma unroll
        for (int e = 0; e < E_NUM; e++) {
#pragma unroll
            for (int off = 16; off > 0; off >>= 1)
                acc[e] += __shfl_xor_sync(0xFFFFFFFFu, acc[e], off);
        }
        if (lane == 0) {
            int e1 = 0; float l1 = acc[0];
#pragma unroll
            for (int e = 1; e < E_NUM; e++) if (acc[e] > l1) { l1 = acc[e]; e1 = e; }
            int e2 = -1; float l2 = -INFINITY;
#pragma unroll
            for (int e = 0; e < E_NUM; e++)
                if (e != e1 && acc[e] > l2) { l2 = acc[e]; e2 = e; }
            float p2  = expf(l2 - l1);
            float inv = 1.f / (1.f + p2);
            g_top2[t * 2] = e1; g_top2[t * 2 + 1] = e2;
            g_wts[t * 2] = inv; g_wts[t * 2 + 1] = p2 * inv;
        }
    }
}

// ----------------------------- scatter (self-histogram, 1 block) -------------
__global__ __launch_bounds__(1024)
void scatter_kernel() {
    __shared__ int s_cnt[E_NUM];
    __shared__ int s_fill[E_NUM];
    int tid = threadIdx.x;
    if (tid < E_NUM) { s_cnt[tid] = 0; s_fill[tid] = 0; }
    __syncthreads();
    for (int t = tid; t < T_TOK; t += 1024) {
        atomicAdd(&s_cnt[g_top2[t * 2]], 1);
        atomicAdd(&s_cnt[g_top2[t * 2 + 1]], 1);
    }
    __syncthreads();
    if (tid == 0) {
        int s = 0;
        for (int e = 0; e < E_NUM; e++) { g_off[e] = s; s += s_cnt[e]; }
        g_off[E_NUM] = s;
    }
    __syncthreads();
    for (int t = tid; t < T_TOK; t += 1024) {
#pragma unroll
        for (int kk = 0; kk < TOPK; kk++) {
            int e = g_top2[t * 2 + kk];
            int p = atomicAdd(&s_fill[e], 1);
            int slot = g_off[e] + p;
            g_tok[slot]   = t;
            g_slotw[slot] = g_wts[t * 2 + kk];
            g_slot[t * 2 + kk] = slot;
        }
    }
}

// ----------------------------- GEMM1 (fp16 mma, dual accum) ------------------
// h[slot, I] = fp16( w_slot * silu(x W1^T) * (x Up^T) ), tile 128x64, K=2048
__global__ __launch_bounds__(256, 2)
void gemm1_mma() {
    extern __shared__ __half sm[];
    int e = blockIdx.z;
    int base = g_off[e], count = g_off[e + 1] - base;
    int m0 = blockIdx.y * BM;
    if (m0 >= count) return;
    int n0 = blockIdx.x * BN;

    int tid = threadIdx.x;
    int wid = tid >> 5, lane = tid & 31;
    int warpM = wid >> 1, warpN = wid & 1;   // 4x2 warps, 32x32 warp tiles
    int g = lane >> 2, tig = lane & 3;

    // loader geometry: 8 threads/row x 16B
    int r  = tid >> 3;            // 0..31
    int hc = (tid & 7) * 8;       // half offset in row

    const __half* Ap[4];
#pragma unroll
    for (int p = 0; p < 4; p++) {
        int mm = m0 + r + 32 * p; if (mm > count - 1) mm = count - 1;
        Ap[p] = g_xh + (size_t)g_tok[base + mm] * H_DIM + hc;
    }
    const __half* B1p[2];
    const __half* B2p[2];
#pragma unroll
    for (int p = 0; p < 2; p++) {
        int nn = n0 + r + 32 * p;
        B1p[p] = g_w1h + ((size_t)e * I_DIM + nn) * H_DIM + hc;
        B2p[p] = g_uph + ((size_t)e * I_DIM + nn) * H_DIM + hc;
    }

    uint32_t sb = smem_u32(sm);
    uint32_t dA[4], dB[2];
#pragma unroll
    for (int p = 0; p < 4; p++) dA[p] = ((r + 32 * p) * SROW2 + hc) * 2;
#pragma unroll
    for (int p = 0; p < 2; p++) dB[p] = ((r + 32 * p) * SROW2 + hc) * 2;

    float accA[2][4][4], accU[2][4][4];
#pragma unroll
    for (int mt = 0; mt < 2; mt++)
#pragma unroll
        for (int nt = 0; nt < 4; nt++)
#pragma unroll
            for (int j = 0; j < 4; j++) { accA[mt][nt][j] = 0.f; accU[mt][nt][j] = 0.f; }

    const int KT = H_DIM / BK;   // 32

#define G1_LOAD(s, kt) do {                                                    \
        uint32_t stgb = sb + (uint32_t)(s) * STG1_B;                           \
        int ko = (kt) * BK;                                                    \
        cp16(stgb + dA[0],                       Ap[0]  + ko);                 \
        cp16(stgb + dA[1],                       Ap[1]  + ko);                 \
        cp16(stgb + dA[2],                       Ap[2]  + ko);                 \
        cp16(stgb + dA[3],                       Ap[3]  + ko);                 \
        cp16(stgb + A_BYTES + dB[0],             B1p[0] + ko);                 \
        cp16(stgb + A_BYTES + dB[1],             B1p[1] + ko);                 \
        cp16(stgb + A_BYTES + B_BYTES + dB[0],   B2p[0] + ko);                 \
        cp16(stgb + A_BYTES + B_BYTES + dB[1],   B2p[1] + ko);                 \
    } while (0)

    G1_LOAD(0, 0); CP_COMMIT();
    G1_LOAD(1, 1); CP_COMMIT();

    for (int kt = 0; kt < KT; kt++) {
        CP_WAIT(1);
        __syncthreads();
        if (kt + 2 < KT) G1_LOAD((kt + 2) % 3, kt + 2);
        CP_COMMIT();

        const __half* S   = sm + (size_t)(kt % 3) * (STG1_B / 2);
        const __half* SA  = S;
        const __half* SB1 = S + A_BYTES / 2;
        const __half* SB2 = S + (A_BYTES + B_BYTES) / 2;

#pragma unroll
        for (int ks = 0; ks < 4; ks++) {
            int kw = ks * 16 + 2 * tig;
            uint32_t a[2][4];
#pragma unroll
            for (int mt = 0; mt < 2; mt++) {
                int row = warpM * 32 + mt * 16 + g;
                a[mt][0] = lds_u32(SA + row * SROW2 + kw);
                a[mt][1] = lds_u32(SA + (row + 8) * SROW2 + kw);
                a[mt][2] = lds_u32(SA + row * SROW2 + kw + 8);
                a[mt][3] = lds_u32(SA + (row + 8) * SROW2 + kw + 8);
            }
#pragma unroll
            for (int nt = 0; nt < 4; nt++) {
                int col = warpN * 32 + nt * 8 + g;
                uint32_t b1[2], b2[2];
                b1[0] = lds_u32(SB1 + col * SROW2 + kw);
                b1[1] = lds_u32(SB1 + col * SROW2 + kw + 8);
                b2[0] = lds_u32(SB2 + col * SROW2 + kw);
                b2[1] = lds_u32(SB2 + col * SROW2 + kw + 8);
#pragma unroll
                for (int mt = 0; mt < 2; mt++) {
                    MMA_F16(accA[mt][nt], a[mt], b1);
                    MMA_F16(accU[mt][nt], a[mt], b2);
                }
            }
        }
    }
#undef G1_LOAD

    // epilogue: w * silu(accA) * accU -> g_h (fp16)
#pragma unroll
    for (int mt = 0; mt < 2; mt++) {
        int row = m0 + warpM * 32 + mt * 16 + g;
        float w0 = (row < count)     ? g_slotw[base + row]     : 0.f;
        float w1 = (row + 8 < count) ? g_slotw[base + row + 8] : 0.f;
#pragma unroll
        for (int nt = 0; nt < 4; nt++) {
            int col = n0 + warpN * 32 + nt * 8 + 2 * tig;
            if (row < count) {
                __half2 v = __floats2half2_rn(
                    w0 * silu_mul(accA[mt][nt][0], accU[mt][nt][0]),
                    w0 * silu_mul(accA[mt][nt][1], accU[mt][nt][1]));
                *(__half2*)(g_h + (size_t)(base + row) * I_DIM + col) = v;
            }
            if (row + 8 < count) {
                __half2 v = __floats2half2_rn(
                    w1 * silu_mul(accA[mt][nt][2], accU[mt][nt][2]),
                    w1 * silu_mul(accA[mt][nt][3], accU[mt][nt][3]));
                *(__half2*)(g_h + (size_t)(base + row + 8) * I_DIM + col) = v;
            }
        }
    }
}

// ----------------------------- GEMM2 (fp16 mma) ------------------------------
// o2[slot, H] = h W2^T,  tile 128x64, K = 1408
__global__ __launch_bounds__(256, 2)
void gemm2_mma() {
    extern __shared__ __half sm[];
    int e = blockIdx.z;
    int base = g_off[e], count = g_off[e + 1] - base;
    int m0 = blockIdx.y * BM;
    if (m0 >= count) return;
    int n0 = blockIdx.x * BN;

    int tid = threadIdx.x;
    int wid = tid >> 5, lane = tid & 31;
    int warpM = wid >> 1, warpN = wid & 1;
    int g = lane >> 2, tig = lane & 3;

    int r  = tid >> 3;
    int hc = (tid & 7) * 8;

    const __half* Ap[4];
#pragma unroll
    for (int p = 0; p < 4; p++) {
        int mm = m0 + r + 32 * p; if (mm > count - 1) mm = count - 1;
        Ap[p] = g_h + (size_t)(base + mm) * I_DIM + hc;
    }
    const __half* Bp[2];
#pragma unroll
    for (int p = 0; p < 2; p++) {
        int nn = n0 + r + 32 * p;
        Bp[p] = g_w2h + ((size_t)e * H_DIM + nn) * I_DIM + hc;
    }

    uint32_t sb = smem_u32(sm);
    uint32_t dA[4], dB[2];
#pragma unroll
    for (int p = 0; p < 4; p++) dA[p] = ((r + 32 * p) * SROW2 + hc) * 2;
#pragma unroll
    for (int p = 0; p < 2; p++) dB[p] = ((r + 32 * p) * SROW2 + hc) * 2;

    float acc[2][4][4];
#pragma unroll
    for (int mt = 0; mt < 2; mt++)
#pragma unroll
        for (int nt = 0; nt < 4; nt++)
#pragma unroll
            for (int j = 0; j < 4; j++) acc[mt][nt][j] = 0.f;

    const int KT = I_DIM / BK;   // 22

#define G2_LOAD(s, kt) do {                                                    \
        uint32_t stgb = sb + (uint32_t)(s) * STG2_B;                           \
        int ko = (kt) * BK;                                                    \
        cp16(stgb + dA[0],           Ap[0] + ko);                              \
        cp16(stgb + dA[1],           Ap[1] + ko);                              \
        cp16(stgb + dA[2],           Ap[2] + ko);                              \
        cp16(stgb + dA[3],           Ap[3] + ko);                              \
        cp16(stgb + A_BYTES + dB[0], Bp[0] + ko);                              \
        cp16(stgb + A_BYTES + dB[1], Bp[1] + ko);                              \
    } while (0)

    G2_LOAD(0, 0); CP_COMMIT();
    G2_LOAD(1, 1); CP_COMMIT();
    G2_LOAD(2, 2); CP_COMMIT();

    for (int kt = 0; kt < KT; kt++) {
        CP_WAIT(2);
        __syncthreads();
        if (kt + 3 < KT) G2_LOAD((kt + 3) & 3, kt + 3);
        CP_COMMIT();

        const __half* S  = sm + (size_t)(kt & 3) * (STG2_B / 2);
        const __half* SA = S;
        const __half* SB = S + A_BYTES / 2;

#pragma unroll
        for (int ks = 0; ks < 4; ks++) {
            int kw = ks * 16 + 2 * tig;
            uint32_t a[2][4];
#pragma unroll
            for (int mt = 0; mt < 2; mt++) {
                int row = warpM * 32 + mt * 16 + g;
                a[mt][0] = lds_u32(SA + row * SROW2 + kw);
                a[mt][1] = lds_u32(SA + (row + 8) * SROW2 + kw);
                a[mt][2] = lds_u32(SA + row * SROW2 + kw + 8);
                a[mt][3] = lds_u32(SA + (row + 8) * SROW2 + kw + 8);
            }
#pragma unroll
            for (int nt = 0; nt < 4; nt++) {
                int col = warpN * 32 + nt * 8 + g;
                uint32_t b[2];
                b[0] = lds_u32(SB + col * SROW2 + kw);
                b[1] = lds_u32(SB + col * SROW2 + kw + 8);
#pragma unroll
                for (int mt = 0; mt < 2; mt++) MMA_F16(acc[mt][nt], a[mt], b);
            }
        }
    }
#undef G2_LOAD

#pragma unroll
    for (int mt = 0; mt < 2; mt++) {
#pragma unroll
        for (int nt = 0; nt < 4; nt++) {
            int row = m0 + warpM * 32 + mt * 16 + g;
            int col = n0 + warpN * 32 + nt * 8 + 2 * tig;
            if (row < count) {
                float2 v = make_float2(acc[mt][nt][0], acc[mt][nt][1]);
                *(float2*)(g_o2 + (size_t)(base + row) * H_DIM + col) = v;
            }
            if (row + 8 < count) {
                float2 v = make_float2(acc[mt][nt][2], acc[mt][nt][3]);
                *(float2*)(g_o2 + (size_t)(base + row + 8) * H_DIM + col) = v;
            }
        }
    }
}

// ----------------------------- combine ---------------------------------------
__global__ void combine_kernel(float4* __restrict__ out) {
    int idx = blockIdx.x * blockDim.x + threadIdx.x;
    int t = idx >> 9;          // H/4 = 512
    int c = idx & 511;
    const float4* r0 = (const float4*)(g_o2 + (size_t)g_slot[t * 2]     * H_DIM) + c;
    const float4* r1 = (const float4*)(g_o2 + (size_t)g_slot[t * 2 + 1] * H_DIM) + c;
    float4 a = *r0, b = *r1, v;
    v.x = a.x + b.x;
    v.y = a.y + b.y;
    v.z = a.z + b.z;
    v.w = a.w + b.w;
    out[idx] = v;
}

// ----------------------------- launch -----------------------------------------
extern "C" void kernel_launch(void* const* d_in, const int* in_sizes, int n_in,
                              void* d_out, int out_size) {
    const float* x  = (const float*)d_in[0];
    const float* gw = (const float*)d_in[1];
    const float* W1 = (const float*)d_in[2];
    const float* Up = (const float*)d_in[3];
    const float* W2 = (const float*)d_in[4];
    float* out = (float*)d_out;

    const int SMEMG = E_NUM * H_DIM * 4;   // 131,072 B (gate)
    const int SMEM1 = 3 * STG1_B;          // 110,592 B
    const int SMEM2 = 4 * STG2_B;          // 110,592 B
    cudaFuncSetAttribute(gate_kernel, cudaFuncAttributeMaxDynamicSharedMemorySize, SMEMG);
    cudaFuncSetAttribute(gemm1_mma,  cudaFuncAttributeMaxDynamicSharedMemorySize, SMEM1);
    cudaFuncSetAttribute(gemm2_mma,  cudaFuncAttributeMaxDynamicSharedMemorySize, SMEM2);

    f2h_all<<<8192, 256>>>((const float4*)W1, (const float4*)Up, (const float4*)W2); // 0
    gate_kernel<<<T_TOK / 32, 256, SMEMG>>>(x, gw);                                  // 1
    scatter_kernel<<<1, 1024>>>();                                                   // 2

    dim3 g1(I_DIM / BN, T_TOK / BM, E_NUM);          // 3: (22, 64, 16)
    gemm1_mma<<<g1, 256, SMEM1>>>();

    dim3 g2(H_DIM / BN, T_TOK / BM, E_NUM);          // 4: (32, 64, 16)
    gemm2_mma<<<g2, 256, SMEM2>>>();

    combine_kernel<<<(T_TOK * H_DIM / 4) / 256, 256>>>((float4*)out);                // 5
}

// round 7
// speedup vs baseline: 1.9010x; 1.0769x over previous
#include <cuda_runtime.h>
#include <cuda_fp16.h>
#include <math.h>
#include <stdint.h>

#define T_TOK 8192
#define H_DIM 2048
#define I_DIM 1408
#define E_NUM 16
#define TOPK  2
#define NSLOT (T_TOK * TOPK)

#define BM 128
#define BN 64
#define BK 64                 // halves per K-slab (128 B/row)
#define SROW2 72              // padded halves per smem row (144 B)
#define A_BYTES (128 * SROW2 * 2)       // 18432
#define B_BYTES (64  * SROW2 * 2)       // 9216
#define STG1_B (A_BYTES + 2 * B_BYTES)  // 36864
#define STG2_B (A_BYTES + B_BYTES)      // 27648

// ----------------------------- device scratch --------------------------------
__device__ __half g_xh [(size_t)T_TOK * H_DIM];
__device__ __half g_w1h[(size_t)E_NUM * I_DIM * H_DIM];
__device__ __half g_uph[(size_t)E_NUM * I_DIM * H_DIM];
__device__ __half g_w2h[(size_t)E_NUM * H_DIM * I_DIM];
__device__ __half g_h  [(size_t)NSLOT * I_DIM];
__device__ float  g_o2 [(size_t)NSLOT * H_DIM];
__device__ int    g_top2[T_TOK * 2];
__device__ float  g_wts [T_TOK * 2];
__device__ int    g_off [E_NUM + 1];
__device__ int    g_tok [NSLOT];
__device__ float  g_slotw[NSLOT];
__device__ int    g_slot[T_TOK * 2];

// ----------------------------- helpers ---------------------------------------
__device__ __forceinline__ uint32_t smem_u32(const void* p) {
    uint32_t a;
    asm("{ .reg .u64 t; cvta.to.shared.u64 t, %1; cvt.u32.u64 %0, t; }" : "=r"(a) : "l"(p));
    return a;
}
__device__ __forceinline__ void cp16(uint32_t dst, const void* src) {
    asm volatile("cp.async.cg.shared.global [%0], [%1], 16;"
                 :: "r"(dst), "l"(__cvta_generic_to_global(src)) : "memory");
}
#define CP_COMMIT() asm volatile("cp.async.commit_group;" ::: "memory")
#define CP_WAIT(n)  asm volatile("cp.async.wait_group %0;" :: "n"(n) : "memory")

#define MMA_F16(d, a, b)                                                       \
    asm volatile("mma.sync.aligned.m16n8k16.row.col.f32.f16.f16.f32 "          \
        "{%0,%1,%2,%3}, {%4,%5,%6,%7}, {%8,%9}, {%0,%1,%2,%3};"                \
        : "+f"((d)[0]), "+f"((d)[1]), "+f"((d)[2]), "+f"((d)[3])               \
        : "r"((a)[0]), "r"((a)[1]), "r"((a)[2]), "r"((a)[3]),                  \
          "r"((b)[0]), "r"((b)[1]))

#define LDSM_X4(r, addr)                                                       \
    asm volatile("ldmatrix.sync.aligned.m8n8.x4.shared.b16 {%0,%1,%2,%3}, [%4];" \
        : "=r"((r)[0]), "=r"((r)[1]), "=r"((r)[2]), "=r"((r)[3]) : "r"(addr))

__device__ __forceinline__ float silu_mul(float a, float u) {
    return (a / (1.f + __expf(-a))) * u;
}

// ----------------------------- fp16 weight conversion ------------------------
__global__ void f2h_all(const float4* __restrict__ w1, const float4* __restrict__ up,
                        const float4* __restrict__ w2) {
    const long n4 = (long)E_NUM * I_DIM * H_DIM / 4;
    long i = blockIdx.x * (long)blockDim.x + threadIdx.x;
    long stride = (long)gridDim.x * blockDim.x;
    for (; i < 3 * n4; i += stride) {
        const float4* src;
        __half* dsth;
        long j;
        if (i < n4)          { src = w1 + i;            dsth = g_w1h; j = i; }
        else if (i < 2 * n4) { src = up + (i - n4);     dsth = g_uph; j = i - n4; }
        else                 { src = w2 + (i - 2 * n4); dsth = g_w2h; j = i - 2 * n4; }
        float4 v = *src;
        __half2 h01 = __floats2half2_rn(v.x, v.y);
        __half2 h23 = __floats2half2_rn(v.z, v.w);
        uint2 u;
        u.x = *(uint32_t*)&h01;
        u.y = *(uint32_t*)&h23;
        *(uint2*)(dsth + j * 4) = u;
    }
}

// ----------------------------- gate (+ x -> fp16) ----------------------------
__global__ __launch_bounds__(256)
void gate_kernel(const float* __restrict__ x, const float* __restrict__ gw) {
    extern __shared__ float sgw[];
    int tid = threadIdx.x;
    for (int i = tid; i < E_NUM * H_DIM / 4; i += 256)
        ((float4*)sgw)[i] = ((const float4*)gw)[i];
    __syncthreads();

    int warp = tid >> 5, lane = tid & 31;
#pragma unroll
    for (int i = 0; i < 4; i++) {
        int t = blockIdx.x * 32 + warp * 4 + i;
        const float* xr = x + (size_t)t * H_DIM;
        float acc[E_NUM];
#pragma unroll
        for (int e = 0; e < E_NUM; e++) acc[e] = 0.f;
        for (int k = lane * 2; k < H_DIM; k += 64) {
            float2 xv = *(const float2*)(xr + k);
            __half2 hv = __floats2half2_rn(xv.x, xv.y);
            *(__half2*)(g_xh + (size_t)t * H_DIM + k) = hv;
#pragma unroll
            for (int e = 0; e < E_NUM; e++) {
                float2 g = *(const float2*)(sgw + e * H_DIM + k);
                acc[e] += xv.x * g.x + xv.y * g.y;
            }
        }
#pragma unroll
        for (int e = 0; e < E_NUM; e++) {
#pragma unroll
            for (int off = 16; off > 0; off >>= 1)
                acc[e] += __shfl_xor_sync(0xFFFFFFFFu, acc[e], off);
        }
        if (lane == 0) {
            int e1 = 0; float l1 = acc[0];
#pragma unroll
            for (int e = 1; e < E_NUM; e++) if (acc[e] > l1) { l1 = acc[e]; e1 = e; }
            int e2 = -1; float l2 = -INFINITY;
#pragma unroll
            for (int e = 0; e < E_NUM; e++)
                if (e != e1 && acc[e] > l2) { l2 = acc[e]; e2 = e; }
            float p2  = expf(l2 - l1);
            float inv = 1.f / (1.f + p2);
            g_top2[t * 2] = e1; g_top2[t * 2 + 1] = e2;
            g_wts[t * 2] = inv; g_wts[t * 2 + 1] = p2 * inv;
        }
    }
}

// ----------------------------- scatter ----------------------------------------
__global__ __launch_bounds__(1024)
void scatter_kernel() {
    __shared__ int s_cnt[E_NUM];
    __shared__ int s_fill[E_NUM];
    int tid = threadIdx.x;
    if (tid < E_NUM) { s_cnt[tid] = 0; s_fill[tid] = 0; }
    __syncthreads();
    for (int t = tid; t < T_TOK; t += 1024) {
        atomicAdd(&s_cnt[g_top2[t * 2]], 1);
        atomicAdd(&s_cnt[g_top2[t * 2 + 1]], 1);
    }
    __syncthreads();
    if (tid == 0) {
        int s = 0;
        for (int e = 0; e < E_NUM; e++) { g_off[e] = s; s += s_cnt[e]; }
        g_off[E_NUM] = s;
    }
    __syncthreads();
    for (int t = tid; t < T_TOK; t += 1024) {
#pragma unroll
        for (int kk = 0; kk < TOPK; kk++) {
            int e = g_top2[t * 2 + kk];
            int p = atomicAdd(&s_fill[e], 1);
            int slot = g_off[e] + p;
            g_tok[slot]   = t;
            g_slotw[slot] = g_wts[t * 2 + kk];
            g_slot[t * 2 + kk] = slot;
        }
    }
}

// ----------------------------- GEMM1 (fp16 mma + ldmatrix) -------------------
__global__ __launch_bounds__(256, 2)
void gemm1_mma() {
    extern __shared__ __half sm[];
    int e = blockIdx.z;
    int base = g_off[e], count = g_off[e + 1] - base;
    int m0 = blockIdx.y * BM;
    if (m0 >= count) return;
    int n0 = blockIdx.x * BN;

    int tid = threadIdx.x;
    int wid = tid >> 5, lane = tid & 31;
    int warpM = wid >> 1, warpN = wid & 1;
    int g = lane >> 2, tig = lane & 3;

    int r  = tid >> 3;
    int hc = (tid & 7) * 8;

    const __half* Ap[4];
#pragma unroll
    for (int p = 0; p < 4; p++) {
        int mm = m0 + r + 32 * p; if (mm > count - 1) mm = count - 1;
        Ap[p] = g_xh + (size_t)g_tok[base + mm] * H_DIM + hc;
    }
    const __half* B1p[2];
    const __half* B2p[2];
#pragma unroll
    for (int p = 0; p < 2; p++) {
        int nn = n0 + r + 32 * p;
        B1p[p] = g_w1h + ((size_t)e * I_DIM + nn) * H_DIM + hc;
        B2p[p] = g_uph + ((size_t)e * I_DIM + nn) * H_DIM + hc;
    }

    uint32_t sb = smem_u32(sm);
    uint32_t dA[4], dB[2];
#pragma unroll
    for (int p = 0; p < 4; p++) dA[p] = ((r + 32 * p) * SROW2 + hc) * 2;
#pragma unroll
    for (int p = 0; p < 2; p++) dB[p] = ((r + 32 * p) * SROW2 + hc) * 2;

    // ldmatrix lane-address bases (bytes within a stage)
    // A (x4): matrices {m0-7 k0-7, m8-15 k0-7, m0-7 k8-15, m8-15 k8-15} -> a0..a3
    uint32_t lmA[2];
#pragma unroll
    for (int mt = 0; mt < 2; mt++) {
        int row = warpM * 32 + mt * 16 + (lane & 15);
        int kh  = (lane >> 4) * 8;
        lmA[mt] = (uint32_t)(row * SROW2 + kh) * 2u;
    }
    // B (x4, non-trans): matrices {n0-7 k0-7, n0-7 k8-15, n8-15 k0-7, n8-15 k8-15}
    //  -> r0=b0(nt even), r1=b1(nt even), r2=b0(nt odd), r3=b1(nt odd)
    uint32_t lmB[2];
#pragma unroll
    for (int p = 0; p < 2; p++) {
        int nrow = warpN * 32 + p * 16 + ((lane >> 4) * 8) + (lane & 7);
        int kh   = ((lane >> 3) & 1) * 8;
        lmB[p] = (uint32_t)(nrow * SROW2 + kh) * 2u;
    }

    float accA[2][4][4], accU[2][4][4];
#pragma unroll
    for (int mt = 0; mt < 2; mt++)
#pragma unroll
        for (int nt = 0; nt < 4; nt++)
#pragma unroll
            for (int j = 0; j < 4; j++) { accA[mt][nt][j] = 0.f; accU[mt][nt][j] = 0.f; }

    const int KT = H_DIM / BK;   // 32

#define G1_LOAD(s, kt) do {                                                    \
        uint32_t stgb = sb + (uint32_t)(s) * STG1_B;                           \
        int ko = (kt) * BK;                                                    \
        cp16(stgb + dA[0],                     Ap[0]  + ko);                   \
        cp16(stgb + dA[1],                     Ap[1]  + ko);                   \
        cp16(stgb + dA[2],                     Ap[2]  + ko);                   \
        cp16(stgb + dA[3],                     Ap[3]  + ko);                   \
        cp16(stgb + A_BYTES + dB[0],           B1p[0] + ko);                   \
        cp16(stgb + A_BYTES + dB[1],           B1p[1] + ko);                   \
        cp16(stgb + A_BYTES + B_BYTES + dB[0], B2p[0] + ko);                   \
        cp16(stgb + A_BYTES + B_BYTES + dB[1], B2p[1] + ko);                   \
    } while (0)

    G1_LOAD(0, 0); CP_COMMIT();
    G1_LOAD(1, 1); CP_COMMIT();

    for (int kt = 0; kt < KT; kt++) {
        CP_WAIT(1);
        __syncthreads();
        if (kt + 2 < KT) G1_LOAD((kt + 2) % 3, kt + 2);
        CP_COMMIT();

        uint32_t stg = sb + (uint32_t)(kt % 3) * STG1_B;
        uint32_t sA  = stg;
        uint32_t sB1 = stg + A_BYTES;
        uint32_t sB2 = stg + A_BYTES + B_BYTES;

#pragma unroll
        for (int ks = 0; ks < 4; ks++) {
            uint32_t ko = ks * 32;        // 16 halves = 32 bytes
            uint32_t a[2][4];
            LDSM_X4(a[0], sA + lmA[0] + ko);
            LDSM_X4(a[1], sA + lmA[1] + ko);
            uint32_t b1f[4][2], b2f[4][2];
#pragma unroll
            for (int p = 0; p < 2; p++) {
                uint32_t rb[4];
                LDSM_X4(rb, sB1 + lmB[p] + ko);
                b1f[2 * p][0] = rb[0]; b1f[2 * p][1] = rb[1];
                b1f[2 * p + 1][0] = rb[2]; b1f[2 * p + 1][1] = rb[3];
                LDSM_X4(rb, sB2 + lmB[p] + ko);
                b2f[2 * p][0] = rb[0]; b2f[2 * p][1] = rb[1];
                b2f[2 * p + 1][0] = rb[2]; b2f[2 * p + 1][1] = rb[3];
            }
#pragma unroll
            for (int nt = 0; nt < 4; nt++) {
#pragma unroll
                for (int mt = 0; mt < 2; mt++) {
                    MMA_F16(accA[mt][nt], a[mt], b1f[nt]);
                    MMA_F16(accU[mt][nt], a[mt], b2f[nt]);
                }
            }
        }
    }
#undef G1_LOAD

#pragma unroll
    for (int mt = 0; mt < 2; mt++) {
        int row = m0 + warpM * 32 + mt * 16 + g;
        float w0 = (row < count)     ? g_slotw[base + row]     : 0.f;
        float w1 = (row + 8 < count) ? g_slotw[base + row + 8] : 0.f;
#pragma unroll
        for (int nt = 0; nt < 4; nt++) {
            int col = n0 + warpN * 32 + nt * 8 + 2 * tig;
            if (row < count) {
                __half2 v = __floats2half2_rn(
                    w0 * silu_mul(accA[mt][nt][0], accU[mt][nt][0]),
                    w0 * silu_mul(accA[mt][nt][1], accU[mt][nt][1]));
                *(__half2*)(g_h + (size_t)(base + row) * I_DIM + col) = v;
            }
            if (row + 8 < count) {
                __half2 v = __floats2half2_rn(
                    w1 * silu_mul(accA[mt][nt][2], accU[mt][nt][2]),
                    w1 * silu_mul(accA[mt][nt][3], accU[mt][nt][3]));
                *(__half2*)(g_h + (size_t)(base + row + 8) * I_DIM + col) = v;
            }
        }
    }
}

// ----------------------------- GEMM2 (fp16 mma + ldmatrix) -------------------
__global__ __launch_bounds__(256, 2)
void gemm2_mma() {
    extern __shared__ __half sm[];
    int e = blockIdx.z;
    int base = g_off[e], count = g_off[e + 1] - base;
    int m0 = blockIdx.y * BM;
    if (m0 >= count) return;
    int n0 = blockIdx.x * BN;

    int tid = threadIdx.x;
    int wid = tid >> 5, lane = tid & 31;
    int warpM = wid >> 1, warpN = wid & 1;
    int g = lane >> 2, tig = lane & 3;

    int r  = tid >> 3;
    int hc = (tid & 7) * 8;

    const __half* Ap[4];
#pragma unroll
    for (int p = 0; p < 4; p++) {
        int mm = m0 + r + 32 * p; if (mm > count - 1) mm = count - 1;
        Ap[p] = g_h + (size_t)(base + mm) * I_DIM + hc;
    }
    const __half* Bp[2];
#pragma unroll
    for (int p = 0; p < 2; p++) {
        int nn = n0 + r + 32 * p;
        Bp[p] = g_w2h + ((size_t)e * H_DIM + nn) * I_DIM + hc;
    }

    uint32_t sb = smem_u32(sm);
    uint32_t dA[4], dB[2];
#pragma unroll
    for (int p = 0; p < 4; p++) dA[p] = ((r + 32 * p) * SROW2 + hc) * 2;
#pragma unroll
    for (int p = 0; p < 2; p++) dB[p] = ((r + 32 * p) * SROW2 + hc) * 2;

    uint32_t lmA[2];
#pragma unroll
    for (int mt = 0; mt < 2; mt++) {
        int row = warpM * 32 + mt * 16 + (lane & 15);
        int kh  = (lane >> 4) * 8;
        lmA[mt] = (uint32_t)(row * SROW2 + kh) * 2u;
    }
    uint32_t lmB[2];
#pragma unroll
    for (int p = 0; p < 2; p++) {
        int nrow = warpN * 32 + p * 16 + ((lane >> 4) * 8) + (lane & 7);
        int kh   = ((lane >> 3) & 1) * 8;
        lmB[p] = (uint32_t)(nrow * SROW2 + kh) * 2u;
    }

    float acc[2][4][4];
#pragma unroll
    for (int mt = 0; mt < 2; mt++)
#pragma unroll
        for (int nt = 0; nt < 4; nt++)
#pragma unroll
            for (int j = 0; j < 4; j++) acc[mt][nt][j] = 0.f;

    const int KT = I_DIM / BK;   // 22

#define G2_LOAD(s, kt) do {                                                    \
        uint32_t stgb = sb + (uint32_t)(s) * STG2_B;                           \
        int ko = (kt) * BK;                                                    \
        cp16(stgb + dA[0],           Ap[0] + ko);                              \
        cp16(stgb + dA[1],           Ap[1] + ko);                              \
        cp16(stgb + dA[2],           Ap[2] + ko);                              \
        cp16(stgb + dA[3],           Ap[3] + ko);                              \
        cp16(stgb + A_BYTES + dB[0], Bp[0] + ko);                              \
        cp16(stgb + A_BYTES + dB[1], Bp[1] + ko);                              \
    } while (0)

    G2_LOAD(0, 0); CP_COMMIT();
    G2_LOAD(1, 1); CP_COMMIT();
    G2_LOAD(2, 2); CP_COMMIT();

    for (int kt = 0; kt < KT; kt++) {
        CP_WAIT(2);
        __syncthreads();
        if (kt + 3 < KT) G2_LOAD((kt + 3) & 3, kt + 3);
        CP_COMMIT();

        uint32_t stg = sb + (uint32_t)(kt & 3) * STG2_B;
        uint32_t sA  = stg;
        uint32_t sB  = stg + A_BYTES;

#pragma unroll
        for (int ks = 0; ks < 4; ks++) {
            uint32_t ko = ks * 32;
            uint32_t a[2][4];
            LDSM_X4(a[0], sA + lmA[0] + ko);
            LDSM_X4(a[1], sA + lmA[1] + ko);
            uint32_t bf[4][2];
#pragma unroll
            for (int p = 0; p < 2; p++) {
                uint32_t rb[4];
                LDSM_X4(rb, sB + lmB[p] + ko);
                bf[2 * p][0] = rb[0]; bf[2 * p][1] = rb[1];
                bf[2 * p + 1][0] = rb[2]; bf[2 * p + 1][1] = rb[3];
            }
#pragma unroll
            for (int nt = 0; nt < 4; nt++) {
#pragma unroll
                for (int mt = 0; mt < 2; mt++) MMA_F16(acc[mt][nt], a[mt], bf[nt]);
            }
        }
    }
#undef G2_LOAD

#pragma unroll
    for (int mt = 0; mt < 2; mt++) {
#pragma unroll
        for (int nt = 0; nt < 4; nt++) {
            int row = m0 + warpM * 32 + mt * 16 + g;
            int col = n0 + warpN * 32 + nt * 8 + 2 * tig;
            if (row < count) {
                float2 v = make_float2(acc[mt][nt][0], acc[mt][nt][1]);
                *(float2*)(g_o2 + (size_t)(base + row) * H_DIM + col) = v;
            }
            if (row + 8 < count) {
                float2 v = make_float2(acc[mt][nt][2], acc[mt][nt][3]);
                *(float2*)(g_o2 + (size_t)(base + row + 8) * H_DIM + col) = v;
            }
        }
    }
}

// ----------------------------- combine ---------------------------------------
__global__ void combine_kernel(float4* __restrict__ out) {
    int idx = blockIdx.x * blockDim.x + threadIdx.x;
    int t = idx >> 9;
    int c = idx & 511;
    const float4* r0 = (const float4*)(g_o2 + (size_t)g_slot[t * 2]     * H_DIM) + c;
    const float4* r1 = (const float4*)(g_o2 + (size_t)g_slot[t * 2 + 1] * H_DIM) + c;
    float4 a = *r0, b = *r1, v;
    v.x = a.x + b.x;
    v.y = a.y + b.y;
    v.z = a.z + b.z;
    v.w = a.w + b.w;
    out[idx] = v;
}

// ----------------------------- launch -----------------------------------------
extern "C" void kernel_launch(void* const* d_in, const int* in_sizes, int n_in,
                              void* d_out, int out_size) {
    const float* x  = (const float*)d_in[0];
    const float* gw = (const float*)d_in[1];
    const float* W1 = (const float*)d_in[2];
    const float* Up = (const float*)d_in[3];
    const float* W2 = (const float*)d_in[4];
    float* out = (float*)d_out;

    const int SMEMG = E_NUM * H_DIM * 4;
    const int SMEM1 = 3 * STG1_B;
    const int SMEM2 = 4 * STG2_B;
    cudaFuncSetAttribute(gate_kernel, cudaFuncAttributeMaxDynamicSharedMemorySize, SMEMG);
    cudaFuncSetAttribute(gemm1_mma,  cudaFuncAttributeMaxDynamicSharedMemorySize, SMEM1);
    cudaFuncSetAttribute(gemm2_mma,  cudaFuncAttributeMaxDynamicSharedMemorySize, SMEM2);

    f2h_all<<<8192, 256>>>((const float4*)W1, (const float4*)Up, (const float4*)W2); // 0
    gate_kernel<<<T_TOK / 32, 256, SMEMG>>>(x, gw);                                  // 1
    scatter_kernel<<<1, 1024>>>();                                                   // 2

    dim3 g1(I_DIM / BN, T_TOK / BM, E_NUM);          // 3: (22, 64, 16)
    gemm1_mma<<<g1, 256, SMEM1>>>();

    dim3 g2(H_DIM / BN, T_TOK / BM, E_NUM);          // 4: (32, 64, 16)
    gemm2_mma<<<g2, 256, SMEM2>>>();

    combine_kernel<<<(T_TOK * H_DIM / 4) / 256, 256>>>((float4*)out);                // 5
}